// round 4
// baseline (speedup 1.0000x reference)
#include <cuda_runtime.h>
#include <math.h>

// ---------------- problem constants (fixed-shape problem) ----------------
constexpr int NNODE = 50000;
constexpr int NEDGE = 800000;
constexpr int FIN   = 256;     // input features
constexpr int H1    = 4;       // heads layer 1
constexpr int C1    = 64;      // channels per head
constexpr int F1    = H1 * C1; // 256 = layer-1 output width
constexpr int C2    = 64;      // layer-2 output width
constexpr float SLOPE = 0.2f;

// ---------------- scratch (static device globals; no allocs) ----------------
__device__ float g_h1[(size_t)NNODE * F1];     // x @ W1
__device__ float g_hbuf[(size_t)NNODE * F1];   // elu(layer1 out + b1)
__device__ float g_h2[(size_t)NNODE * C2];     // hbuf @ W2
__device__ float g_as1[NNODE * H1];
__device__ float g_ad1[NNODE * H1];
__device__ float g_as2[NNODE];
__device__ float g_ad2[NNODE];
__device__ int   g_deg[NNODE];
__device__ int   g_cur[NNODE];
__device__ int   g_offs[NNODE + 1];
__device__ int   g_bsums[64];
__device__ int   g_csr[NEDGE];                 // src ids grouped by dst

__device__ __forceinline__ float leakyr(float v) { return v > 0.f ? v : SLOPE * v; }

// ---------------- CSR construction (counting sort by dst) ----------------
__global__ void zero_ints_kernel() {
    int i = blockIdx.x * blockDim.x + threadIdx.x;
    if (i < NNODE) { g_deg[i] = 0; g_cur[i] = 0; }
}

// edge_index is int32 (JAX default x64-disabled downgrades the requested int64).
__global__ void count_deg_kernel(const int* __restrict__ ei) {
    int e = blockIdx.x * blockDim.x + threadIdx.x;
    if (e < NEDGE) {
        int d = ei[NEDGE + e];
        if (d >= 0 && d < NNODE) atomicAdd(&g_deg[d], 1);
    }
}

constexpr int SCAN_T = 1024;
constexpr int SCAN_NB = (NNODE + SCAN_T - 1) / SCAN_T;  // 49

__global__ void scan_block_kernel() {
    __shared__ int sh[SCAN_T];
    int gid = blockIdx.x * SCAN_T + threadIdx.x;
    int v = (gid < NNODE) ? g_deg[gid] : 0;
    sh[threadIdx.x] = v;
    __syncthreads();
    for (int off = 1; off < SCAN_T; off <<= 1) {
        int t = (threadIdx.x >= off) ? sh[threadIdx.x - off] : 0;
        __syncthreads();
        sh[threadIdx.x] += t;
        __syncthreads();
    }
    if (gid < NNODE) g_offs[gid] = sh[threadIdx.x] - v;   // exclusive
    if (threadIdx.x == SCAN_T - 1) g_bsums[blockIdx.x] = sh[threadIdx.x];
}

__global__ void scan_sums_kernel() {
    if (threadIdx.x == 0 && blockIdx.x == 0) {
        int run = 0;
        for (int i = 0; i < SCAN_NB; i++) { int v = g_bsums[i]; g_bsums[i] = run; run += v; }
    }
}

__global__ void scan_add_kernel() {
    int gid = blockIdx.x * SCAN_T + threadIdx.x;
    if (gid < NNODE) g_offs[gid] += g_bsums[blockIdx.x];
    if (gid == 0) g_offs[NNODE] = NEDGE;
}

__global__ void scatter_kernel(const int* __restrict__ ei) {
    int e = blockIdx.x * blockDim.x + threadIdx.x;
    if (e < NEDGE) {
        int d = ei[NEDGE + e];
        int s = ei[e];
        if (d >= 0 && d < NNODE && s >= 0 && s < NNODE) {
            int p = g_offs[d] + atomicAdd(&g_cur[d], 1);
            if (p >= 0 && p < NEDGE) g_csr[p] = s;
        }
    }
}

// ---------------- fp32 SGEMM: C[M,N] = A[M,K] @ B[K,N] ----------------
// 128x128 tile, BK=8, 256 threads, 8x8 microtile.
// MODE 0: A = arg (x), C = g_h1.  MODE 1: A = g_hbuf, C = g_h2.
template <int MODE>
__global__ void __launch_bounds__(256)
sgemm_kernel(const float* __restrict__ Aarg, const float* __restrict__ B,
             int M, int Nn, int K) {
    const float* __restrict__ A = (MODE == 0) ? Aarg : g_hbuf;
    float* __restrict__ C = (MODE == 0) ? g_h1 : g_h2;

    constexpr int BM = 128, BN = 128, BK = 8;
    __shared__ float As[BK][BM];
    __shared__ float Bs[BK][BN];

    int tid = threadIdx.x;
    int tx = tid & 15;        // N dim, 8 outputs each
    int ty = tid >> 4;        // M dim, 8 outputs each
    int rowBase = blockIdx.y * BM;
    int colBase = blockIdx.x * BN;

    int aRow = tid >> 1;            // 0..127
    int aCol = (tid & 1) * 4;       // 0 / 4
    int bRow = tid >> 5;            // 0..7
    int bCol = (tid & 31) * 4;      // 0..124

    float acc[8][8];
#pragma unroll
    for (int i = 0; i < 8; i++)
#pragma unroll
        for (int j = 0; j < 8; j++) acc[i][j] = 0.f;

    for (int k0 = 0; k0 < K; k0 += BK) {
        float4 av = make_float4(0.f, 0.f, 0.f, 0.f);
        if (rowBase + aRow < M)
            av = *(const float4*)&A[(size_t)(rowBase + aRow) * K + k0 + aCol];
        As[aCol + 0][aRow] = av.x;
        As[aCol + 1][aRow] = av.y;
        As[aCol + 2][aRow] = av.z;
        As[aCol + 3][aRow] = av.w;

        float4 bv;
        if (colBase + bCol + 3 < Nn) {
            bv = *(const float4*)&B[(size_t)(k0 + bRow) * Nn + colBase + bCol];
        } else {
            float t0 = 0.f, t1 = 0.f, t2 = 0.f, t3 = 0.f;
            if (colBase + bCol + 0 < Nn) t0 = B[(size_t)(k0 + bRow) * Nn + colBase + bCol + 0];
            if (colBase + bCol + 1 < Nn) t1 = B[(size_t)(k0 + bRow) * Nn + colBase + bCol + 1];
            if (colBase + bCol + 2 < Nn) t2 = B[(size_t)(k0 + bRow) * Nn + colBase + bCol + 2];
            bv = make_float4(t0, t1, t2, t3);
        }
        *(float4*)&Bs[bRow][bCol] = bv;
        __syncthreads();

#pragma unroll
        for (int kk = 0; kk < BK; kk++) {
            float a[8], b[8];
            *(float4*)&a[0] = *(float4*)&As[kk][ty * 8];
            *(float4*)&a[4] = *(float4*)&As[kk][ty * 8 + 4];
            *(float4*)&b[0] = *(float4*)&Bs[kk][tx * 8];
            *(float4*)&b[4] = *(float4*)&Bs[kk][tx * 8 + 4];
#pragma unroll
            for (int i = 0; i < 8; i++)
#pragma unroll
                for (int j = 0; j < 8; j++) acc[i][j] = fmaf(a[i], b[j], acc[i][j]);
        }
        __syncthreads();
    }

#pragma unroll
    for (int i = 0; i < 8; i++) {
        int r = rowBase + ty * 8 + i;
        if (r >= M) break;
#pragma unroll
        for (int j = 0; j < 8; j++) {
            int c = colBase + tx * 8 + j;
            if (c < Nn) C[(size_t)r * Nn + c] = acc[i][j];
        }
    }
}

// ---------------- attention coefficients: a[n,h] = <h[n,h,:], att[h,:]> ----------------
// one warp per (node,head); channel = 64
template <int L>
__global__ void attn_coeff_kernel(const float* __restrict__ atts,
                                  const float* __restrict__ attd) {
    const float* __restrict__ h = (L == 0) ? g_h1 : g_h2;
    float* __restrict__ oS = (L == 0) ? g_as1 : g_as2;
    float* __restrict__ oD = (L == 0) ? g_ad1 : g_ad2;
    const int H = (L == 0) ? H1 : 1;

    int w = (blockIdx.x * blockDim.x + threadIdx.x) >> 5;
    int lane = threadIdx.x & 31;
    if (w >= NNODE * H) return;
    int hh = w % H;  // works for H=1 too
    const float* hp = h + (size_t)w * 64;  // node*H*64 + hh*64 == w*64

    float x1 = hp[lane], x2 = hp[lane + 32];
    float ss = x1 * atts[hh * 64 + lane] + x2 * atts[hh * 64 + lane + 32];
    float sd = x1 * attd[hh * 64 + lane] + x2 * attd[hh * 64 + lane + 32];
#pragma unroll
    for (int o = 16; o; o >>= 1) {
        ss += __shfl_xor_sync(0xFFFFFFFFu, ss, o);
        sd += __shfl_xor_sync(0xFFFFFFFFu, sd, o);
    }
    if (lane == 0) { oS[w] = ss; oD[w] = sd; }
}

// ---------------- layer-1 aggregation: one block (256 thr) per dst node ----------------
// thread t owns output channel t (head = t>>6). Self-loop handled inline.
__global__ void __launch_bounds__(256)
agg1_kernel(const float* __restrict__ b1) {
    int n = blockIdx.x;
    int t = threadIdx.x;
    int h = t >> 6;
    int beg = g_offs[n], end = g_offs[n + 1];
    float ad = g_ad1[n * H1 + h];

    float eself = leakyr(g_as1[n * H1 + h] + ad);
    float m = eself;
    for (int i = beg; i < end; i++) {
        int s = g_csr[i];
        m = fmaxf(m, leakyr(g_as1[s * H1 + h] + ad));
    }

    float ex = __expf(eself - m);
    float ssum = ex;
    float acc = ex * g_h1[(size_t)n * F1 + t];
    for (int i = beg; i < end; i++) {
        int s = g_csr[i];
        float e = leakyr(g_as1[s * H1 + h] + ad);
        float w = __expf(e - m);
        ssum += w;
        acc = fmaf(w, g_h1[(size_t)s * F1 + t], acc);
    }
    float o = acc / (ssum + 1e-16f) + b1[t];
    g_hbuf[(size_t)n * F1 + t] = (o > 0.f) ? o : (__expf(o) - 1.f);
}

// ---------------- layer-2 aggregation: 4 nodes per 256-thread block ----------------
__global__ void __launch_bounds__(256)
agg2_kernel(const float* __restrict__ b2, float* __restrict__ out) {
    int t = threadIdx.x;
    int g = t >> 6, c = t & 63;
    int n = blockIdx.x * 4 + g;
    if (n >= NNODE) return;
    int beg = g_offs[n], end = g_offs[n + 1];
    float ad = g_ad2[n];

    float eself = leakyr(g_as2[n] + ad);
    float m = eself;
    for (int i = beg; i < end; i++) {
        int s = g_csr[i];
        m = fmaxf(m, leakyr(g_as2[s] + ad));
    }

    float ex = __expf(eself - m);
    float ssum = ex;
    float acc = ex * g_h2[(size_t)n * C2 + c];
    for (int i = beg; i < end; i++) {
        int s = g_csr[i];
        float e = leakyr(g_as2[s] + ad);
        float w = __expf(e - m);
        ssum += w;
        acc = fmaf(w, g_h2[(size_t)s * C2 + c], acc);
    }
    float o = acc / (ssum + 1e-16f) + b2[c];
    out[(size_t)n * C2 + c] = (o > 0.f) ? o : (__expf(o) - 1.f);
}

// ---------------- launch ----------------
extern "C" void kernel_launch(void* const* d_in, const int* in_sizes, int n_in,
                              void* d_out, int out_size) {
    const float* x    = (const float*)d_in[0];
    const int*   ei   = (const int*)d_in[1];      // int32 edge_index [2, E]
    const float* W1   = (const float*)d_in[2];
    const float* as1w = (const float*)d_in[3];
    const float* ad1w = (const float*)d_in[4];
    const float* b1   = (const float*)d_in[5];
    const float* W2   = (const float*)d_in[6];
    const float* as2w = (const float*)d_in[7];
    const float* ad2w = (const float*)d_in[8];
    const float* b2   = (const float*)d_in[9];
    float*       out  = (float*)d_out;

    (void)in_sizes; (void)n_in; (void)out_size;

    // ---- CSR by destination (counting sort), built fresh each call ----
    zero_ints_kernel<<<(NNODE + 255) / 256, 256>>>();
    count_deg_kernel<<<(NEDGE + 255) / 256, 256>>>(ei);
    scan_block_kernel<<<SCAN_NB, SCAN_T>>>();
    scan_sums_kernel<<<1, 32>>>();
    scan_add_kernel<<<SCAN_NB, SCAN_T>>>();
    scatter_kernel<<<(NEDGE + 255) / 256, 256>>>(ei);

    // ---- layer 1 ----
    {
        dim3 grid(F1 / 128, (NNODE + 127) / 128);
        sgemm_kernel<0><<<grid, 256>>>(x, W1, NNODE, F1, FIN);
    }
    attn_coeff_kernel<0><<<(NNODE * H1 + 7) / 8, 256>>>(as1w, ad1w);
    agg1_kernel<<<NNODE, 256>>>(b1);

    // ---- layer 2 ----
    {
        dim3 grid(1, (NNODE + 127) / 128);
        sgemm_kernel<1><<<grid, 256>>>(nullptr, W2, NNODE, C2, F1);
    }
    attn_coeff_kernel<1><<<(NNODE + 7) / 8, 256>>>(as2w, ad2w);
    agg2_kernel<<<(NNODE + 3) / 4, 256>>>(b2, out);
}